// round 16
// baseline (speedup 1.0000x reference)
#include <cuda_runtime.h>
#include <cuda_fp16.h>
#include <mma.h>
#include <math.h>
#include <cstdint>

using namespace nvcuda;

// ---------------- problem constants ----------------
#define BATCH 64
#define TT    48
#define PIX   225
#define PP    256                    // padded 16-wide rows: y,x valid in 1..15
#define MTOT  (BATCH * PP)           // 16384
#define HID   128
#define MPC   448                    // M rows per CTA
#define MT    37                     // 37*448 = 16576 >= 16384
#define NTHR  448                    // 14 warps: 7m x 2n, warp tile 64x64

#define WSCALE   64.0f
#define INVSCALE 0.015625f

// ---------------- smem geometry ----------------
#define AROWS (MPC + 34)             // 482 rows (halo 17 + 17)
#define ALDM  40                     // 32 ch + 8 pad (80B rows, conflict-free)
#define WLDM  136                    // 128 cols + 8 pad (272B rows)
#define ACCLDM 132
#define ABYTES (AROWS * ALDM * 2)            // 38560 (single buffer)
#define WBYTES (9 * 32 * WLDM * 2)           // 78336
#define MAIN_BYTES (ABYTES + 2 * WBYTES)     // 195232
#define EPI_BYTES  (256 * ACCLDM * 4)        // 135168 pass tile (< MAIN: safe)
#define SMEM_BYTES MAIN_BYTES

// ---------------- device state (no allocation APIs) ----------------
__device__ __half g_enc[(size_t)TT * MTOT * 64];
__device__ __half g_h1[2][(size_t)MTOT * HID];
__device__ __half g_h2[2][(size_t)MTOT * HID];
__device__ float g_c1[(size_t)MTOT * HID];
__device__ float g_c2[(size_t)MTOT * HID];
// weights: [kc32][row = tap*32 + k][n'(512)]   n' = hc*4 + gate
__device__ __half g_Wp0[(size_t)6 * 288 * 512];
__device__ __half g_Wp1[(size_t)8 * 288 * 512];

// ---------------- async-copy helpers ----------------
__device__ __forceinline__ uint32_t smem_u32(const void* p) {
    uint32_t a;
    asm("{ .reg .u64 t; cvta.to.shared.u64 t, %1; cvt.u32.u64 %0, t; }" : "=r"(a) : "l"(p));
    return a;
}
__device__ __forceinline__ void cp16(uint32_t dst, const void* src) {
    asm volatile("cp.async.cg.shared.global [%0], [%1], 16;" :: "r"(dst), "l"(src));
}
__device__ __forceinline__ void cp_commit() { asm volatile("cp.async.commit_group;"); }
template<int N> __device__ __forceinline__ void cp_wait() {
    asm volatile("cp.async.wait_group %0;" :: "n"(N));
}

// ---------------------------------------------------------------------------
// prep: weights -> scaled single fp16, [kc32][row = tap*32 + k][512] layout
// ---------------------------------------------------------------------------
__global__ void prep_w(const float* __restrict__ W, __half* __restrict__ Wp,
                       int NKC)
{
    const int CTOT = NKC * 32;
    long idx = (long)blockIdx.x * blockDim.x + threadIdx.x;
    long tot = (long)NKC * 9 * 32 * 512;
    if (idx >= tot) return;
    int n   = (int)(idx & 511);
    int k   = (int)((idx >> 9) & 31);
    int tap = (int)((idx >> 14) % 9);
    int kc  = (int)(idx / (9L << 14));
    int hc = n >> 2, gate = n & 3;
    int oc = gate * HID + hc;
    int c  = kc * 32 + k;
    float w = W[((long)oc * CTOT + c) * 9 + tap] * WSCALE;
    Wp[((size_t)kc * 288 + tap * 32 + k) * 512 + n] = __float2half(w);
}

// ---------------------------------------------------------------------------
// prep: encoder -> 16-wide padded rows [t][m][64] fp16 (ring zero)
// ---------------------------------------------------------------------------
__global__ void prep_enc(const float* __restrict__ enc, __half* __restrict__ e16)
{
    size_t idx = (size_t)blockIdx.x * blockDim.x + threadIdx.x;
    size_t tot = (size_t)TT * MTOT * 64;
    if (idx >= tot) return;
    int c = (int)(idx & 63);
    int m = (int)((idx >> 6) % MTOT);
    int t = (int)(idx / ((size_t)MTOT * 64));
    int b = m >> 8, pid = m & 255;
    int y = pid >> 4, x = pid & 15;
    float v = 0.f;
    if (y >= 1 && x >= 1)       // y,x <= 15 automatic
        v = enc[(((size_t)b * TT + t) * 64 + c) * PIX + (y - 1) * 15 + (x - 1)];
    e16[idx] = __float2half(v);
}

// ---------------------------------------------------------------------------
// Fused step: implicit-GEMM conv, 9 shifted taps (s = dy*16+dx), single fp16
// pass, K-chunk 32. A single-buffered, W double-buffered with separate
// cp.async groups (W prefetch overlaps compute; A exposure is small).
// Block: 448 threads / 14 warps (7m x 2n), CTA 448M x 128N, warp 64x64.
// Grid (37, 4) = 148 CTAs = exactly one wave.
// ---------------------------------------------------------------------------
template<int NKC, int NX, int XSTR>
__global__ __launch_bounds__(NTHR, 1)
void step_kernel(const __half* __restrict__ xin,
                 const __half* __restrict__ hin,
                 const __half* __restrict__ Wp, const float* __restrict__ bias,
                 float* __restrict__ cst,
                 __half* __restrict__ hout)
{
    extern __shared__ __align__(16) __half smem[];
    __half* sA    = smem;                              // [482][40]
    __half* sW[2] = { smem + ABYTES / 2,
                      smem + ABYTES / 2 + WBYTES / 2 };
    float* sAcc = (float*)smem;                        // reuse for epilogue

    const int m0  = blockIdx.x * MPC;
    const int nt  = blockIdx.y;
    const int n0  = nt * 128;
    const int tid = threadIdx.x;
    const int wid = tid >> 5;
    const int wm  = wid >> 1;     // 0..6 : warp M offset wm*64
    const int wn  = wid & 1;      // 0..1 : warp N offset wn*64

    const uint32_t sAu    = smem_u32(sA);
    const uint32_t sWu[2] = { smem_u32(sW[0]), smem_u32(sW[1]) };

    // ---- A staging (single buffer): rows m0-17 .. m0+464 ----
    auto stage_A = [&](int kc) {
        const __half* src_; int coff, stride;
        if (kc < NX) { src_ = xin; coff = kc * 32; stride = XSTR; }
        else         { src_ = hin; coff = (kc - NX) * 32; stride = HID; }
        for (int u = tid; u < AROWS * 4; u += NTHR) {
            int r = u >> 2, q = u & 3;
            int m = m0 - 17 + r;
            if (m >= 0 && m < MTOT) {
                cp16(sAu + (uint32_t)r * 80 + q * 16,
                     src_ + (size_t)m * stride + coff + q * 8);
            } else {
                *(uint4*)(sA + r * ALDM + q * 8) = make_uint4(0, 0, 0, 0);
            }
        }
        cp_commit();
    };
    // ---- W staging into buffer b ----
    auto stage_W = [&](int kc, int b) {
        const __half* wsrc = Wp + (size_t)kc * (288 * 512) + n0;
        for (int u = tid; u < 288 * 16; u += NTHR) {
            int row = u >> 4, nl = u & 15;
            cp16(sWu[b] + (uint32_t)row * 272 + nl * 16, wsrc + (size_t)row * 512 + nl * 8);
        }
        cp_commit();
    };

    wmma::fragment<wmma::accumulator, 16, 16, 16, float> acc[4][4];
    #pragma unroll
    for (int f = 0; f < 4; f++)
        #pragma unroll
        for (int j = 0; j < 4; j++) wmma::fill_fragment(acc[f][j], 0.f);

    // prologue: group{A0,W0}, group{W1}
    stage_A(0);                       // commits inside (group with only A0)
    stage_W(0, 0);                    // group W0
    if (NKC > 1) stage_W(1, 1);       // group W1

    for (int kc = 0; kc < NKC; kc++) {
        const int b = kc & 1;
        if (kc + 1 < NKC) cp_wait<1>(); else cp_wait<0>();
        __syncthreads();

        // ---- 9 taps x 2 k-steps, fully unrolled (R11 inner loop) ----
        const __half* A = sA;
        const __half* W = sW[b];
        #pragma unroll
        for (int tap = 0; tap < 9; tap++) {
            const int s = (tap / 3) * 16 + (tap % 3);
            #pragma unroll
            for (int ks = 0; ks < 2; ks++) {
                wmma::fragment<wmma::matrix_a, 16, 16, 16, __half, wmma::row_major> af[4];
                #pragma unroll
                for (int f = 0; f < 4; f++)
                    wmma::load_matrix_sync(af[f],
                        A + (wm * 64 + f * 16 + s) * ALDM + ks * 16, ALDM);
                wmma::fragment<wmma::matrix_b, 16, 16, 16, __half, wmma::row_major> bf[4];
                #pragma unroll
                for (int j = 0; j < 4; j++)
                    wmma::load_matrix_sync(bf[j],
                        W + (tap * 32 + ks * 16) * WLDM + wn * 64 + j * 16, WLDM);
                #pragma unroll
                for (int f = 0; f < 4; f++)
                    #pragma unroll
                    for (int j = 0; j < 4; j++)
                        wmma::mma_sync(acc[f][j], af[f], bf[j], acc[f][j]);
            }
        }
        __syncthreads();   // reads of sA / sW[b] done

        if (kc + 1 < NKC) {
            stage_A(kc + 1);                       // group A(kc+1)
            if (kc + 2 < NKC) stage_W(kc + 2, b);  // group W(kc+2) into freed buf
        }
    }

    // ---- epilogue in two passes (rows 0-255: wm 0-3; rows 256-447: wm 4-6) ----
    #pragma unroll
    for (int pass = 0; pass < 2; pass++) {
        const int nrows = pass ? (MPC - 256) : 256;
        if (pass == 0 ? (wm < 4) : (wm >= 4)) {
            const int rbase = pass ? (wm - 4) * 64 : wm * 64;
            #pragma unroll
            for (int f = 0; f < 4; f++)
                #pragma unroll
                for (int j = 0; j < 4; j++)
                    wmma::store_matrix_sync(sAcc + (rbase + f * 16) * ACCLDM + wn * 64 + j * 16,
                                            acc[f][j], ACCLDM, wmma::mem_row_major);
        }
        __syncthreads();

        for (int e = tid; e < nrows * 32; e += NTHR) {
            int mr = e >> 5, hcl = e & 31;
            int m = m0 + pass * 256 + mr;
            if (m >= MTOT) continue;
            int pid = m & 255;
            int y = pid >> 4, x = pid & 15;
            if (y < 1 || x < 1) continue;           // ring rows stay zero
            int hc = nt * 32 + hcl;
            const float* zr = &sAcc[mr * ACCLDM + hcl * 4];
            float zi = zr[0] * INVSCALE + bias[hc];
            float zf = zr[1] * INVSCALE + bias[HID + hc];
            float zo = zr[2] * INVSCALE + bias[2 * HID + hc];
            float zg = zr[3] * INVSCALE + bias[3 * HID + hc];
            float ig = __fdividef(1.f, 1.f + __expf(-zi));
            float fg = __fdividef(1.f, 1.f + __expf(-zf));
            float og = __fdividef(1.f, 1.f + __expf(-zo));
            float eg = __expf(2.f * zg);
            float gg = 1.f - __fdividef(2.f, eg + 1.f);     // tanh, inf-safe
            size_t idx = (size_t)m * HID + hc;
            float cn = fg * cst[idx] + ig * gg;
            cst[idx] = cn;
            float ec = __expf(2.f * cn);
            float hv = og * (1.f - __fdividef(2.f, ec + 1.f));
            hout[idx] = __float2half(hv);
        }
        __syncthreads();
    }
}

// ---------------------------------------------------------------------------
// Final dense (fp32): out[b,o] = feat . Wd + bd, feat = fp16 h2 (16-wide rows)
// ---------------------------------------------------------------------------
__global__ __launch_bounds__(128)
void dense_kernel(const __half* __restrict__ h2,
                  const float* __restrict__ Wd, const float* __restrict__ bd,
                  float* __restrict__ out)
{
    __shared__ float sf[1024];
    const int b = blockIdx.x;
    const int o = threadIdx.x;
    float s0 = 0.f, s1 = 0.f, s2 = 0.f, s3 = 0.f;
    const int KTOT = HID * PIX;                // 28800
    for (int k0 = 0; k0 < KTOT; k0 += 1024) {
        __syncthreads();
        for (int i = o; i < 1024; i += 128) {
            int k = k0 + i;
            float v = 0.f;
            if (k < KTOT) {
                int hc = k / PIX, p = k % PIX;
                size_t m = (size_t)b * PP + (p / 15 + 1) * 16 + (p % 15 + 1);
                v = __half2float(h2[m * HID + hc]);
            }
            sf[i] = v;
        }
        __syncthreads();
        int kmax = min(1024, KTOT - k0);
        for (int kk = 0; kk < kmax; kk += 4) {
            s0 += sf[kk + 0] * Wd[(long)(k0 + kk + 0) * 128 + o];
            s1 += sf[kk + 1] * Wd[(long)(k0 + kk + 1) * 128 + o];
            s2 += sf[kk + 2] * Wd[(long)(k0 + kk + 2) * 128 + o];
            s3 += sf[kk + 3] * Wd[(long)(k0 + kk + 3) * 128 + o];
        }
    }
    out[b * 128 + o] = (s0 + s1) + (s2 + s3) + bd[o];
}

// ---------------------------------------------------------------------------
extern "C" void kernel_launch(void* const* d_in, const int* in_sizes, int n_in,
                              void* d_out, int out_size)
{
    const float* enc = (const float*)d_in[0];
    const float* W0  = (const float*)d_in[1];
    const float* b0  = (const float*)d_in[2];
    const float* W1  = (const float*)d_in[3];
    const float* b1  = (const float*)d_in[4];
    const float* Wd  = (const float*)d_in[5];
    const float* bd  = (const float*)d_in[6];
    float* out = (float*)d_out;

    __half *e16, *h1, *h2, *Wp0, *Wp1;
    float *c1, *c2;
    cudaGetSymbolAddress((void**)&e16, g_enc);
    cudaGetSymbolAddress((void**)&h1, g_h1);
    cudaGetSymbolAddress((void**)&h2, g_h2);
    cudaGetSymbolAddress((void**)&c1, g_c1);
    cudaGetSymbolAddress((void**)&c2, g_c2);
    cudaGetSymbolAddress((void**)&Wp0, g_Wp0);
    cudaGetSymbolAddress((void**)&Wp1, g_Wp1);

    const size_t HS = (size_t)MTOT * HID;

    cudaMemsetAsync(h1, 0, 2 * HS * sizeof(__half), 0);
    cudaMemsetAsync(h2, 0, 2 * HS * sizeof(__half), 0);
    cudaMemsetAsync(c1, 0, HS * sizeof(float), 0);
    cudaMemsetAsync(c2, 0, HS * sizeof(float), 0);

    prep_w<<<(6 * 9 * 32 * 512 + 255) / 256, 256>>>(W0, Wp0, 6);
    prep_w<<<(8 * 9 * 32 * 512 + 255) / 256, 256>>>(W1, Wp1, 8);
    {
        size_t tot = (size_t)TT * MTOT * 64;
        prep_enc<<<(unsigned)((tot + 255) / 256), 256>>>(enc, e16);
    }

    cudaFuncSetAttribute(step_kernel<6, 2, 64>,
                         cudaFuncAttributeMaxDynamicSharedMemorySize, SMEM_BYTES);
    cudaFuncSetAttribute(step_kernel<8, 4, 128>,
                         cudaFuncAttributeMaxDynamicSharedMemorySize, SMEM_BYTES);

    dim3 grid(MT, 4);
    for (int t = 0; t < TT; t++) {
        const int rd = t & 1, wr = rd ^ 1;
        step_kernel<6, 2, 64><<<grid, NTHR, SMEM_BYTES>>>(
            e16 + (size_t)t * MTOT * 64,
            h1 + (size_t)rd * HS,
            Wp0, b0, c1,
            h1 + (size_t)wr * HS);
        step_kernel<8, 4, 128><<<grid, NTHR, SMEM_BYTES>>>(
            h1 + (size_t)wr * HS,
            h2 + (size_t)rd * HS,
            Wp1, b1, c2,
            h2 + (size_t)wr * HS);
    }
    // final h2 in ping 0 (wr of t=47)
    dense_kernel<<<BATCH, 128>>>(h2, Wd, bd, out);
}

// round 17
// speedup vs baseline: 3.3013x; 3.3013x over previous
#include <cuda_runtime.h>
#include <cuda_fp16.h>
#include <mma.h>
#include <math.h>
#include <cstdint>

using namespace nvcuda;

// ---------------- problem constants ----------------
#define BATCH 64
#define TT    48
#define PIX   225
#define PP    256                    // 16-wide padded rows: y=0 row, x=0 col are pad
#define MTOT  (BATCH * PP)           // 16384
#define HID   128
#define MPC   256                    // M rows per CTA
#define MT    64                     // 16384/256

#define WSCALE   64.0f
#define INVSCALE 0.015625f

// ---------------- smem geometry (R11 proven, 16-wide halo) ----------------
#define AROWS (MPC + 34)             // 290 rows (halo 17 + 17)
#define ALDM  40                     // 32 ch + 8 pad (80B rows, conflict-free)
#define WLDM  136                    // 128 cols + 8 pad (272B rows)
#define ACCLDM 132
#define ABYTES (AROWS * ALDM * 2)            // 23200
#define WBYTES (9 * 32 * WLDM * 2)           // 78336
#define MAIN_BYTES (2 * ABYTES + 2 * WBYTES) // 203072
#define EPI_BYTES  (MPC * ACCLDM * 4)        // 135168 (< MAIN: safe)
#define SMEM_BYTES MAIN_BYTES

// ---------------- device state (no allocation APIs) ----------------
__device__ __half g_enc[(size_t)TT * MTOT * 64];
__device__ __half g_h1[2][(size_t)MTOT * HID];
__device__ __half g_h2[2][(size_t)MTOT * HID];
__device__ float g_c1[(size_t)MTOT * HID];
__device__ float g_c2[(size_t)MTOT * HID];
// weights: [kc32][row = tap*32 + k][n'(512)]   n' = hc*4 + gate
__device__ __half g_Wp0[(size_t)6 * 288 * 512];
__device__ __half g_Wp1[(size_t)8 * 288 * 512];

// ---------------- async-copy helpers ----------------
__device__ __forceinline__ uint32_t smem_u32(const void* p) {
    uint32_t a;
    asm("{ .reg .u64 t; cvta.to.shared.u64 t, %1; cvt.u32.u64 %0, t; }" : "=r"(a) : "l"(p));
    return a;
}
__device__ __forceinline__ void cp16(uint32_t dst, const void* src) {
    asm volatile("cp.async.cg.shared.global [%0], [%1], 16;" :: "r"(dst), "l"(src));
}
__device__ __forceinline__ void cp_commit() { asm volatile("cp.async.commit_group;"); }
template<int N> __device__ __forceinline__ void cp_wait() {
    asm volatile("cp.async.wait_group %0;" :: "n"(N));
}

// ---------------------------------------------------------------------------
// prep: weights -> scaled single fp16, [kc32][row = tap*32 + k][512] layout
// ---------------------------------------------------------------------------
__global__ void prep_w(const float* __restrict__ W, __half* __restrict__ Wp,
                       int NKC)
{
    const int CTOT = NKC * 32;
    long idx = (long)blockIdx.x * blockDim.x + threadIdx.x;
    long tot = (long)NKC * 9 * 32 * 512;
    if (idx >= tot) return;
    int n   = (int)(idx & 511);
    int k   = (int)((idx >> 9) & 31);
    int tap = (int)((idx >> 14) % 9);
    int kc  = (int)(idx / (9L << 14));
    int hc = n >> 2, gate = n & 3;
    int oc = gate * HID + hc;
    int c  = kc * 32 + k;
    float w = W[((long)oc * CTOT + c) * 9 + tap] * WSCALE;
    Wp[((size_t)kc * 288 + tap * 32 + k) * 512 + n] = __float2half(w);
}

// ---------------------------------------------------------------------------
// prep: encoder -> 16-wide padded rows [t][m][64] fp16 (pad row/col zero)
// ---------------------------------------------------------------------------
__global__ void prep_enc(const float* __restrict__ enc, __half* __restrict__ e16)
{
    size_t idx = (size_t)blockIdx.x * blockDim.x + threadIdx.x;
    size_t tot = (size_t)TT * MTOT * 64;
    if (idx >= tot) return;
    int c = (int)(idx & 63);
    int m = (int)((idx >> 6) & (MTOT - 1));
    int t = (int)(idx / ((size_t)MTOT * 64));
    int b = m >> 8, pid = m & 255;
    int y = pid >> 4, x = pid & 15;
    float v = 0.f;
    if (y >= 1 && x >= 1)                       // y,x <= 15 automatic
        v = enc[(((size_t)b * TT + t) * 64 + c) * PIX + (y - 1) * 15 + (x - 1)];
    e16[idx] = __float2half(v);
}

// ---------------------------------------------------------------------------
// Fused step (R11 mainloop, 16-wide geometry): implicit-GEMM conv, 9 shifted
// taps (s = dy*16+dx), single scaled-fp16 pass, K-chunk 32, cp.async double
// buffer, fully unrolled MMA region.
// Block: 256 threads / 8 warps (4m x 2n), CTA 256M x 128N, warp 64x64.
// Grid (64, 4) = 256 CTAs. 1 CTA/SM.
// ---------------------------------------------------------------------------
template<int NKC, int NX, int XSTR>
__global__ __launch_bounds__(256, 1)
void step_kernel(const __half* __restrict__ xin,
                 const __half* __restrict__ hin,
                 const __half* __restrict__ Wp, const float* __restrict__ bias,
                 float* __restrict__ cst,
                 __half* __restrict__ hout)
{
    extern __shared__ __align__(16) __half smem[];
    __half* sA[2] = { smem, smem + ABYTES / 2 };
    __half* sW[2] = { smem + ABYTES, smem + ABYTES + WBYTES / 2 };
    float* sAcc = (float*)smem;                  // reuse for epilogue

    const int m0  = blockIdx.x * MPC;
    const int nt  = blockIdx.y;
    const int n0  = nt * 128;
    const int tid = threadIdx.x;
    const int wid = tid >> 5;
    const int wm  = wid >> 1;     // 0..3 : warp M offset wm*64
    const int wn  = wid & 1;      // 0..1 : warp N offset wn*64

    const uint32_t sAu[2] = { smem_u32(sA[0]), smem_u32(sA[1]) };
    const uint32_t sWu[2] = { smem_u32(sW[0]), smem_u32(sW[1]) };

    // ---- staging routine (cp.async) for chunk kc into buffer b ----
    auto prefetch = [&](int kc, int b) {
        const __half* src_; int coff, stride;
        if (kc < NX) { src_ = xin; coff = kc * 32; stride = XSTR; }
        else         { src_ = hin; coff = (kc - NX) * 32; stride = HID; }
        // A: 290 rows x 4 x 16B, rows m0-17 .. m0+272
        for (int u = tid; u < AROWS * 4; u += 256) {
            int r = u >> 2, q = u & 3;
            int m = m0 - 17 + r;
            if (m >= 0 && m < MTOT) {
                cp16(sAu[b] + (uint32_t)r * 80 + q * 16,
                     src_ + (size_t)m * stride + coff + q * 8);
            } else {
                *(uint4*)(sA[b] + r * ALDM + q * 8) = make_uint4(0, 0, 0, 0);
            }
        }
        // W: 288 rows x 16 x 16B (row-linear source)
        const __half* wsrc = Wp + (size_t)kc * (288 * 512) + n0;
        for (int u = tid; u < 288 * 16; u += 256) {
            int row = u >> 4, nl = u & 15;
            cp16(sWu[b] + (uint32_t)row * 272 + nl * 16, wsrc + (size_t)row * 512 + nl * 8);
        }
        cp_commit();
    };

    wmma::fragment<wmma::accumulator, 16, 16, 16, float> acc[4][4];
    #pragma unroll
    for (int f = 0; f < 4; f++)
        #pragma unroll
        for (int j = 0; j < 4; j++) wmma::fill_fragment(acc[f][j], 0.f);

    prefetch(0, 0);

    for (int kc = 0; kc < NKC; kc++) {
        const int b = kc & 1;
        if (kc + 1 < NKC) prefetch(kc + 1, b ^ 1);
        if (kc + 1 < NKC) cp_wait<1>(); else cp_wait<0>();
        __syncthreads();

        // ---- 9 taps x 2 k-steps, fully unrolled (cross-stage ILP) ----
        const __half* A = sA[b];
        const __half* W = sW[b];
        #pragma unroll
        for (int tap = 0; tap < 9; tap++) {
            const int s = (tap / 3) * 16 + (tap % 3);   // dy*16 + dx
            #pragma unroll
            for (int ks = 0; ks < 2; ks++) {
                wmma::fragment<wmma::matrix_a, 16, 16, 16, __half, wmma::row_major> af[4];
                #pragma unroll
                for (int f = 0; f < 4; f++)
                    wmma::load_matrix_sync(af[f],
                        A + (wm * 64 + f * 16 + s) * ALDM + ks * 16, ALDM);
                wmma::fragment<wmma::matrix_b, 16, 16, 16, __half, wmma::row_major> bf[4];
                #pragma unroll
                for (int j = 0; j < 4; j++)
                    wmma::load_matrix_sync(bf[j],
                        W + (tap * 32 + ks * 16) * WLDM + wn * 64 + j * 16, WLDM);
                #pragma unroll
                for (int f = 0; f < 4; f++)
                    #pragma unroll
                    for (int j = 0; j < 4; j++)
                        wmma::mma_sync(acc[f][j], af[f], bf[j], acc[f][j]);
            }
        }
        __syncthreads();   // all reads of buf b done before it is refilled
    }

    // ---- epilogue: acc -> smem -> unscale -> LSTM update -> fp16 state ----
    #pragma unroll
    for (int f = 0; f < 4; f++)
        #pragma unroll
        for (int j = 0; j < 4; j++)
            wmma::store_matrix_sync(sAcc + (wm * 64 + f * 16) * ACCLDM + wn * 64 + j * 16,
                                    acc[f][j], ACCLDM, wmma::mem_row_major);
    __syncthreads();

    for (int e = tid; e < MPC * 32; e += 256) {
        int mr = e >> 5, hcl = e & 31;
        int m = m0 + mr;
        int pid = m & 255;
        int y = pid >> 4, x = pid & 15;
        if (y < 1 || x < 1) continue;           // pad row/col stay zero
        int hc = nt * 32 + hcl;
        const float* zr = &sAcc[mr * ACCLDM + hcl * 4];
        float zi = zr[0] * INVSCALE + bias[hc];
        float zf = zr[1] * INVSCALE + bias[HID + hc];
        float zo = zr[2] * INVSCALE + bias[2 * HID + hc];
        float zg = zr[3] * INVSCALE + bias[3 * HID + hc];
        float ig = __fdividef(1.f, 1.f + __expf(-zi));
        float fg = __fdividef(1.f, 1.f + __expf(-zf));
        float og = __fdividef(1.f, 1.f + __expf(-zo));
        float eg = __expf(2.f * zg);
        float gg = 1.f - __fdividef(2.f, eg + 1.f);         // tanh, inf-safe
        size_t idx = (size_t)m * HID + hc;
        float cn = fg * cst[idx] + ig * gg;
        cst[idx] = cn;
        float ec = __expf(2.f * cn);
        float hv = og * (1.f - __fdividef(2.f, ec + 1.f));
        hout[idx] = __float2half(hv);
    }
}

// ---------------------------------------------------------------------------
// Final dense (fp32): out[b,o] = feat . Wd + bd, feat = fp16 h2 (16-wide rows)
// ---------------------------------------------------------------------------
__global__ __launch_bounds__(128)
void dense_kernel(const __half* __restrict__ h2,
                  const float* __restrict__ Wd, const float* __restrict__ bd,
                  float* __restrict__ out)
{
    __shared__ float sf[1024];
    const int b = blockIdx.x;
    const int o = threadIdx.x;
    float s0 = 0.f, s1 = 0.f, s2 = 0.f, s3 = 0.f;
    const int KTOT = HID * PIX;                // 28800
    for (int k0 = 0; k0 < KTOT; k0 += 1024) {
        __syncthreads();
        for (int i = o; i < 1024; i += 128) {
            int k = k0 + i;
            float v = 0.f;
            if (k < KTOT) {
                int hc = k / PIX, p = k % PIX;
                size_t m = (size_t)b * PP + (p / 15 + 1) * 16 + (p % 15 + 1);
                v = __half2float(h2[m * HID + hc]);
            }
            sf[i] = v;
        }
        __syncthreads();
        int kmax = min(1024, KTOT - k0);
        for (int kk = 0; kk < kmax; kk += 4) {
            s0 += sf[kk + 0] * Wd[(long)(k0 + kk + 0) * 128 + o];
            s1 += sf[kk + 1] * Wd[(long)(k0 + kk + 1) * 128 + o];
            s2 += sf[kk + 2] * Wd[(long)(k0 + kk + 2) * 128 + o];
            s3 += sf[kk + 3] * Wd[(long)(k0 + kk + 3) * 128 + o];
        }
    }
    out[b * 128 + o] = (s0 + s1) + (s2 + s3) + bd[o];
}

// ---------------------------------------------------------------------------
extern "C" void kernel_launch(void* const* d_in, const int* in_sizes, int n_in,
                              void* d_out, int out_size)
{
    const float* enc = (const float*)d_in[0];
    const float* W0  = (const float*)d_in[1];
    const float* b0  = (const float*)d_in[2];
    const float* W1  = (const float*)d_in[3];
    const float* b1  = (const float*)d_in[4];
    const float* Wd  = (const float*)d_in[5];
    const float* bd  = (const float*)d_in[6];
    float* out = (float*)d_out;

    __half *e16, *h1, *h2, *Wp0, *Wp1;
    float *c1, *c2;
    cudaGetSymbolAddress((void**)&e16, g_enc);
    cudaGetSymbolAddress((void**)&h1, g_h1);
    cudaGetSymbolAddress((void**)&h2, g_h2);
    cudaGetSymbolAddress((void**)&c1, g_c1);
    cudaGetSymbolAddress((void**)&c2, g_c2);
    cudaGetSymbolAddress((void**)&Wp0, g_Wp0);
    cudaGetSymbolAddress((void**)&Wp1, g_Wp1);

    const size_t HS = (size_t)MTOT * HID;

    cudaMemsetAsync(h1, 0, 2 * HS * sizeof(__half), 0);
    cudaMemsetAsync(h2, 0, 2 * HS * sizeof(__half), 0);
    cudaMemsetAsync(c1, 0, HS * sizeof(float), 0);
    cudaMemsetAsync(c2, 0, HS * sizeof(float), 0);

    prep_w<<<(6 * 9 * 32 * 512 + 255) / 256, 256>>>(W0, Wp0, 6);
    prep_w<<<(8 * 9 * 32 * 512 + 255) / 256, 256>>>(W1, Wp1, 8);
    {
        size_t tot = (size_t)TT * MTOT * 64;
        prep_enc<<<(unsigned)((tot + 255) / 256), 256>>>(enc, e16);
    }

    cudaFuncSetAttribute(step_kernel<6, 2, 64>,
                         cudaFuncAttributeMaxDynamicSharedMemorySize, SMEM_BYTES);
    cudaFuncSetAttribute(step_kernel<8, 4, 128>,
                         cudaFuncAttributeMaxDynamicSharedMemorySize, SMEM_BYTES);

    dim3 grid(MT, 4);
    for (int t = 0; t < TT; t++) {
        const int rd = t & 1, wr = rd ^ 1;
        step_kernel<6, 2, 64><<<grid, 256, SMEM_BYTES>>>(
            e16 + (size_t)t * MTOT * 64,
            h1 + (size_t)rd * HS,
            Wp0, b0, c1,
            h1 + (size_t)wr * HS);
        step_kernel<8, 4, 128><<<grid, 256, SMEM_BYTES>>>(
            h1 + (size_t)wr * HS,
            h2 + (size_t)rd * HS,
            Wp1, b1, c2,
            h2 + (size_t)wr * HS);
    }
    // final h2 in ping 0 (wr of t=47)
    dense_kernel<<<BATCH, 128>>>(h2, Wd, bd, out);
}